// round 9
// baseline (speedup 1.0000x reference)
#include <cuda_runtime.h>
#include <math.h>

#define GXN 128
#define GYN 128
#define NA 9
#define NCELLS (32 * 128 * 128)            // 524288
#define TPB 128
#define NWARPS (TPB / 32)                  // 4
#define TILE_CELLS 128                     // cells per tile (one CTA-tile)
#define NTILES (NCELLS / TILE_CELLS)       // 4096
#define TILE_FLOATS (TILE_CELLS * 45)      // 5760
#define TILE_BYTES (TILE_FLOATS * 4)       // 23040
#define GRID 592                           // 4 CTAs/SM * 148 SMs — one wave

__device__ double g_acc[5];
__device__ unsigned int g_count = 0;

__device__ __forceinline__ unsigned smem_u32(const void* p) {
    return (unsigned)__cvta_generic_to_shared(p);
}

__device__ __forceinline__ void mbar_init(unsigned mbar, unsigned count) {
    asm volatile("mbarrier.init.shared.b64 [%0], %1;" :: "r"(mbar), "r"(count) : "memory");
}
__device__ __forceinline__ void mbar_expect_tx(unsigned mbar, unsigned bytes) {
    asm volatile("mbarrier.arrive.expect_tx.shared.b64 _, [%0], %1;"
                 :: "r"(mbar), "r"(bytes) : "memory");
}
__device__ __forceinline__ void bulk_copy(unsigned dst_smem, const void* gsrc,
                                          unsigned bytes, unsigned mbar) {
    asm volatile(
        "cp.async.bulk.shared::cta.global.mbarrier::complete_tx::bytes [%0], [%1], %2, [%3];"
        :: "r"(dst_smem), "l"(gsrc), "r"(bytes), "r"(mbar) : "memory");
}
__device__ __forceinline__ void mbar_wait(unsigned mbar, unsigned phase) {
    unsigned done;
    asm volatile(
        "{\n\t.reg .pred p;\n\t"
        "mbarrier.try_wait.parity.acquire.cta.shared::cta.b64 p, [%1], %2;\n\t"
        "selp.b32 %0, 1, 0, p;\n\t}"
        : "=r"(done) : "r"(mbar), "r"(phase) : "memory");
    if (!done) {
        asm volatile(
            "{\n\t.reg .pred P1;\n\t"
            "WAIT_LOOP_%=:\n\t"
            "mbarrier.try_wait.parity.acquire.cta.shared::cta.b64 P1, [%0], %1, 0x989680;\n\t"
            "@P1 bra.uni WAIT_DONE_%=;\n\t"
            "bra.uni WAIT_LOOP_%=;\n\t"
            "WAIT_DONE_%=:\n\t}"
            :: "r"(mbar), "r"(phase) : "memory");
    }
}

__global__ __launch_bounds__(TPB) void loss_kernel(
    const float* __restrict__ out,
    const float* __restrict__ target,
    float* __restrict__ o)
{
    extern __shared__ float s_buf[];   // 2 * 5760 floats = 46080 B

    __shared__ float s_cellp[NWARPS][32][8];      // 4096 B
    __shared__ float s_red[NWARPS][5];
    __shared__ int s_islast;
    __shared__ __align__(8) unsigned long long s_mbar[2];

    const int tid = threadIdx.x;
    const int warp = tid >> 5;
    const int lane = tid & 31;
    const unsigned FULL = 0xFFFFFFFFu;

    const unsigned mbar0 = smem_u32(&s_mbar[0]);
    const unsigned mbar1 = smem_u32(&s_mbar[1]);
    const unsigned dst0 = smem_u32(s_buf);
    const unsigned dst1 = smem_u32(s_buf + TILE_FLOATS);

    // Number of tiles this block handles: tiles bid, bid+GRID, bid+2*GRID, ...
    const int bid = blockIdx.x;
    const int nt = (NTILES - 1 - bid) / GRID + 1;

    if (tid == 0) {
        mbar_init(mbar0, 1);
        mbar_init(mbar1, 1);
    }
    __syncthreads();

    if (tid == 0) {
        // Prologue: copies for tiles 0 and 1 of this block's sequence
        mbar_expect_tx(mbar0, TILE_BYTES);
        bulk_copy(dst0, out + (size_t)bid * TILE_FLOATS, TILE_BYTES, mbar0);
        if (nt > 1) {
            mbar_expect_tx(mbar1, TILE_BYTES);
            bulk_copy(dst1, out + (size_t)(bid + GRID) * TILE_FLOATS, TILE_BYTES, mbar1);
        }
    }

    float acc_allloss = 0.0f;
    float acc_jbb = 0.0f;
    float acc_huhuh = 0.0f;
    float acc_zsd = 0.0f;
    float acc_npos = 0.0f;

    const float FOUR_OVER_PI2 = 4.0f / (3.14159265358979323846f * 3.14159265358979323846f);

    for (int i = 0; i < nt; i++) {
        const int tile = bid + i * GRID;
        const int buf = i & 1;
        const unsigned phase = (i >> 1) & 1u;
        float* wbuf = s_buf + buf * TILE_FLOATS + warp * (32 * 45);

        // ---- Prefetch this lane's target fields BEFORE the wait ----
        const int cellc = tile * TILE_CELLS + warp * 32 + lane;
        const float* st = target + (size_t)cellc * 18;
        const float2 st01 = __ldg(reinterpret_cast<const float2*>(st));
        const float2 st23 = __ldg(reinterpret_cast<const float2*>(st + 2));
        const float st5 = __ldg(st + 5);

        mbar_wait(buf ? mbar1 : mbar0, phase);
        __syncwarp();

        const bool pos = st5 > 0.8f;
        const unsigned m = __ballot_sync(FULL, pos);
        const int nP = __popc(m);

        if (pos) {
            const int off = __popc(m & ((1u << lane) - 1u));
            const int gy = cellc & 127;
            const int gx = (cellc >> 7) & 127;

            const float ax1 = st01.x - st23.x * 0.5f;
            const float ax2 = st01.x + st23.x * 0.5f;
            const float ay1 = st01.y - st23.y * 0.5f;
            const float ay2 = st01.y + st23.y * 0.5f;
            const float atana = atanf(__fdividef(ax2 - ax1, ay2 - ay1));
            const float zx = (float)gx * (1.0f / GXN) + 1.0f / (2.0f * GXN);
            const float zy = (float)gy * (1.0f / GYN) + 1.0f / (2.0f * GYN);

            float* p = s_cellp[warp][off];
            p[0] = ax1; p[1] = ax2; p[2] = ay1; p[3] = ay2;
            p[4] = atana; p[5] = zx; p[6] = zy;
            p[7] = __int_as_float(lane * 45);
            acc_npos += 1.0f;
        } else {
            const float* s = wbuf + lane * 45;
            #pragma unroll
            for (int a = 0; a < NA; a++) {
                const float obj = s[a * 5 + 4];
                acc_zsd += obj * obj;
            }
        }
        __syncwarp();

        // ---- Heavy sweep: nP*9 work items across this warp's 32 cells ----
        const int items = nP * NA;
        for (int b = 0; b < items; b += 32) {
            const int ii = b + lane;
            if (ii < items) {
                const int r = ii / 9;
                const int a = ii - r * 9;
                const float* p = s_cellp[warp][r];
                const float ax1 = p[0], ax2 = p[1], ay1 = p[2], ay2 = p[3];
                const float atana = p[4], zx = p[5], zy = p[6];
                const int coff = __float_as_int(p[7]);

                const float* s = wbuf + coff + a * 5;
                const float o0 = s[0];
                const float o1 = s[1];
                const float o2 = s[2];
                const float o3 = s[3];
                const float obj = s[4];

                const float area_a = (ax2 - ax1) * (ay2 - ay1);
                const float acx = (ax1 + ax2) * 0.5f;
                const float acy = (ay1 + ay2) * 0.5f;

                const float bcx = o0 - 0.5f + zx;
                const float bcy = o1 - 0.5f + zy;
                const float bw  = o2 - 0.5f + (1.0f / GXN);
                const float bh  = o3 - 0.5f + (1.0f / GYN);
                const float bx1 = bcx - bw * 0.5f;
                const float bx2 = bcx + bw * 0.5f;
                const float by1 = bcy - bh * 0.5f;
                const float by2 = bcy + bh * 0.5f;

                const float iw = fminf(ax2, bx2) - fmaxf(ax1, bx1);
                const float ih = fminf(ay2, by2) - fmaxf(ay1, by1);
                const float cross = (iw > 0.0f && ih > 0.0f) ? iw * ih : 0.0f;
                const float area_b = (bx2 - bx1) * (by2 - by1);
                const float uni = area_a + area_b - cross;
                const float iou = __fdividef(cross, uni + 1e-6f);

                const float dx = bcx - acx;
                const float dy = bcy - acy;
                const float d2 = dx * dx + dy * dy;

                const float cw = fmaxf(ax2, bx2) - fminf(ax1, bx1);
                const float ch = fmaxf(ay2, by2) - fminf(ay1, by1);
                const float c2 = cw * cw + ch * ch;

                const float diou = iou - __fdividef(d2, c2);

                const float da = atana - atanf(__fdividef(bx2 - bx1, by2 - by1));
                const float v = FOUR_OVER_PI2 * da * da;
                const float alpha = __fdividef(v, 1.0f - iou + v);
                const float los = 1.0f - (diou - alpha * v);

                const float om = 1.0f - obj;
                acc_allloss += los + om;
                acc_jbb += iou;
                acc_huhuh += om;
                acc_zsd += om * om;
            }
        }

        // ---- Buffer free; refill with tile i+2 ----
        __syncthreads();
        if (i + 2 < nt && tid == 0) {
            const unsigned mb = buf ? mbar1 : mbar0;
            const unsigned db = buf ? dst1 : dst0;
            mbar_expect_tx(mb, TILE_BYTES);
            bulk_copy(db, out + (size_t)(bid + (i + 2) * GRID) * TILE_FLOATS,
                      TILE_BYTES, mb);
        }
    }

    // ---- Block reduction (once per block): 4 sums + pos count ----
    float vals[5];
    vals[0] = acc_allloss;
    vals[1] = acc_jbb;
    vals[2] = acc_huhuh;
    vals[3] = acc_zsd;
    vals[4] = acc_npos;

    #pragma unroll
    for (int kk = 0; kk < 5; kk++) {
        float v = vals[kk];
        v += __shfl_xor_sync(FULL, v, 16);
        v += __shfl_xor_sync(FULL, v, 8);
        v += __shfl_xor_sync(FULL, v, 4);
        v += __shfl_xor_sync(FULL, v, 2);
        v += __shfl_xor_sync(FULL, v, 1);
        vals[kk] = v;
    }
    if (lane == 0) {
        #pragma unroll
        for (int kk = 0; kk < 5; kk++) s_red[warp][kk] = vals[kk];
    }
    __syncthreads();

    if (warp == 0 && lane < 5) {
        float v = 0.0f;
        #pragma unroll
        for (int w = 0; w < NWARPS; w++) v += s_red[w][lane];
        atomicAdd(&g_acc[lane], (double)v);
    }
    __syncthreads();

    // ---- Last block finalizes and resets for next graph replay ----
    if (tid == 0) {
        __threadfence();
        const unsigned done = atomicAdd(&g_count, 1u);
        s_islast = (done == (unsigned)(gridDim.x - 1)) ? 1 : 0;
    }
    __syncthreads();

    if (s_islast && tid == 0) {
        const double a0 = atomicAdd(&g_acc[0], 0.0);
        const double a1 = atomicAdd(&g_acc[1], 0.0);
        const double a2 = atomicAdd(&g_acc[2], 0.0);
        const double a3 = atomicAdd(&g_acc[3], 0.0);
        const double npos = atomicAdd(&g_acc[4], 0.0);

        const double jsq = npos * (double)NA;
        const double qit = ((double)NCELLS - npos) * (double)NA;
        o[0] = (float)(a0 / jsq + a3 / (jsq + qit));
        o[1] = (float)(a1 / jsq);
        o[2] = (float)(a2 / jsq);

        g_acc[0] = 0.0; g_acc[1] = 0.0; g_acc[2] = 0.0;
        g_acc[3] = 0.0; g_acc[4] = 0.0;
        __threadfence();
        g_count = 0u;
    }
}

extern "C" void kernel_launch(void* const* d_in, const int* in_sizes, int n_in,
                              void* d_out, int out_size) {
    const float* out_t = (const float*)d_in[0];
    const float* target = (const float*)d_in[1];
    float* o = (float*)d_out;

    const int smem_bytes = 2 * TILE_FLOATS * (int)sizeof(float); // 46080
    static int configured = 0;
    if (!configured) {
        cudaFuncSetAttribute(loss_kernel,
                             cudaFuncAttributeMaxDynamicSharedMemorySize,
                             smem_bytes);
        configured = 1;
    }
    loss_kernel<<<GRID, TPB, smem_bytes>>>(out_t, target, o);
}

// round 10
// speedup vs baseline: 1.0413x; 1.0413x over previous
#include <cuda_runtime.h>
#include <math.h>

#define GXN 128
#define GYN 128
#define NA 9
#define NCELLS (32 * 128 * 128)            // 524288
#define TPB 128
#define NWARPS (TPB / 32)                  // 4
#define TILE_CELLS 128
#define NTILES (NCELLS / TILE_CELLS)       // 4096
#define OUT_FLOATS (TILE_CELLS * 45)       // 5760
#define TGT_FLOATS (TILE_CELLS * 18)       // 2304
#define BUF_FLOATS (OUT_FLOATS + TGT_FLOATS) // 8064
#define OUT_BYTES (OUT_FLOATS * 4)         // 23040
#define TGT_BYTES (TGT_FLOATS * 4)         // 9216
#define BUF_BYTES (BUF_FLOATS * 4)         // 32256
#define GRID 444                           // 3 CTAs/SM * 148 SMs — one wave

__device__ double g_acc[5];
__device__ unsigned int g_count = 0;

__device__ __forceinline__ unsigned smem_u32(const void* p) {
    return (unsigned)__cvta_generic_to_shared(p);
}
__device__ __forceinline__ void mbar_init(unsigned mbar, unsigned count) {
    asm volatile("mbarrier.init.shared.b64 [%0], %1;" :: "r"(mbar), "r"(count) : "memory");
}
__device__ __forceinline__ void mbar_expect_tx(unsigned mbar, unsigned bytes) {
    asm volatile("mbarrier.arrive.expect_tx.shared.b64 _, [%0], %1;"
                 :: "r"(mbar), "r"(bytes) : "memory");
}
__device__ __forceinline__ void bulk_copy(unsigned dst_smem, const void* gsrc,
                                          unsigned bytes, unsigned mbar) {
    asm volatile(
        "cp.async.bulk.shared::cta.global.mbarrier::complete_tx::bytes [%0], [%1], %2, [%3];"
        :: "r"(dst_smem), "l"(gsrc), "r"(bytes), "r"(mbar) : "memory");
}
__device__ __forceinline__ void mbar_wait(unsigned mbar, unsigned phase) {
    unsigned done;
    asm volatile(
        "{\n\t.reg .pred p;\n\t"
        "mbarrier.try_wait.parity.acquire.cta.shared::cta.b64 p, [%1], %2;\n\t"
        "selp.b32 %0, 1, 0, p;\n\t}"
        : "=r"(done) : "r"(mbar), "r"(phase) : "memory");
    if (!done) {
        asm volatile(
            "{\n\t.reg .pred P1;\n\t"
            "WAIT_LOOP_%=:\n\t"
            "mbarrier.try_wait.parity.acquire.cta.shared::cta.b64 P1, [%0], %1, 0x989680;\n\t"
            "@P1 bra.uni WAIT_DONE_%=;\n\t"
            "bra.uni WAIT_LOOP_%=;\n\t"
            "WAIT_DONE_%=:\n\t}"
            :: "r"(mbar), "r"(phase) : "memory");
    }
}

__global__ __launch_bounds__(TPB) void loss_kernel(
    const float* __restrict__ out,
    const float* __restrict__ target,
    float* __restrict__ o)
{
    extern __shared__ float s_buf[];   // 2 * 8064 floats = 64512 B
    // layout per buffer: [0:5760) out tile, [5760:8064) target tile

    __shared__ float s_cellp[NWARPS][32][8];
    __shared__ float s_red[NWARPS][5];
    __shared__ int s_islast;
    __shared__ __align__(8) unsigned long long s_mbar[2];

    const int tid = threadIdx.x;
    const int warp = tid >> 5;
    const int lane = tid & 31;
    const unsigned FULL = 0xFFFFFFFFu;

    const unsigned mbar0 = smem_u32(&s_mbar[0]);
    const unsigned mbar1 = smem_u32(&s_mbar[1]);

    const int bid = blockIdx.x;
    const int nt = (bid < NTILES % GRID) ? (NTILES / GRID + 1) : (NTILES / GRID);

    if (tid == 0) {
        mbar_init(mbar0, 1);
        mbar_init(mbar1, 1);
    }
    __syncthreads();

    if (tid == 0) {
        // Prologue: copies for tiles 0 and 1 of this block's sequence
        {
            const unsigned d = smem_u32(s_buf);
            mbar_expect_tx(mbar0, BUF_BYTES);
            bulk_copy(d, out + (size_t)bid * OUT_FLOATS, OUT_BYTES, mbar0);
            bulk_copy(d + OUT_BYTES, target + (size_t)bid * TGT_FLOATS, TGT_BYTES, mbar0);
        }
        if (nt > 1) {
            const unsigned d = smem_u32(s_buf + BUF_FLOATS);
            const size_t t1 = (size_t)(bid + GRID);
            mbar_expect_tx(mbar1, BUF_BYTES);
            bulk_copy(d, out + t1 * OUT_FLOATS, OUT_BYTES, mbar1);
            bulk_copy(d + OUT_BYTES, target + t1 * TGT_FLOATS, TGT_BYTES, mbar1);
        }
    }

    float acc_allloss = 0.0f;
    float acc_jbb = 0.0f;
    float acc_huhuh = 0.0f;
    float acc_zsd = 0.0f;
    float acc_npos = 0.0f;

    const float FOUR_OVER_PI2 = 4.0f / (3.14159265358979323846f * 3.14159265358979323846f);

    for (int i = 0; i < nt; i++) {
        const int tile = bid + i * GRID;
        const int buf = i & 1;
        const unsigned phase = (i >> 1) & 1u;
        float* bb = s_buf + buf * BUF_FLOATS;
        float* wbuf = bb + warp * (32 * 45);                   // this warp's out cells
        const float* stg = bb + OUT_FLOATS + (warp * 32 + lane) * 18;  // own cell target

        mbar_wait(buf ? mbar1 : mbar0, phase);

        const int cellc = tile * TILE_CELLS + warp * 32 + lane;
        const float st5 = stg[5];
        const bool pos = st5 > 0.8f;
        const unsigned m = __ballot_sync(FULL, pos);
        const int nP = __popc(m);

        if (pos) {
            const int off = __popc(m & ((1u << lane) - 1u));
            const int gy = cellc & 127;
            const int gx = (cellc >> 7) & 127;

            const float st0 = stg[0];
            const float st1 = stg[1];
            const float st2 = stg[2];
            const float st3 = stg[3];

            const float ax1 = st0 - st2 * 0.5f;
            const float ax2 = st0 + st2 * 0.5f;
            const float ay1 = st1 - st3 * 0.5f;
            const float ay2 = st1 + st3 * 0.5f;
            const float atana = atanf(__fdividef(ax2 - ax1, ay2 - ay1));
            const float zx = (float)gx * (1.0f / GXN) + 1.0f / (2.0f * GXN);
            const float zy = (float)gy * (1.0f / GYN) + 1.0f / (2.0f * GYN);

            float* p = s_cellp[warp][off];
            p[0] = ax1; p[1] = ax2; p[2] = ay1; p[3] = ay2;
            p[4] = atana; p[5] = zx; p[6] = zy;
            p[7] = __int_as_float(lane * 45);
            acc_npos += 1.0f;
        } else {
            const float* s = wbuf + lane * 45;
            #pragma unroll
            for (int a = 0; a < NA; a++) {
                const float obj = s[a * 5 + 4];
                acc_zsd += obj * obj;
            }
        }
        __syncwarp();

        // ---- Heavy sweep: nP*9 work items across this warp's 32 cells ----
        const int items = nP * NA;
        for (int b = 0; b < items; b += 32) {
            const int ii = b + lane;
            if (ii < items) {
                const int r = ii / 9;
                const int a = ii - r * 9;
                const float* p = s_cellp[warp][r];
                const float ax1 = p[0], ax2 = p[1], ay1 = p[2], ay2 = p[3];
                const float atana = p[4], zx = p[5], zy = p[6];
                const int coff = __float_as_int(p[7]);

                const float* s = wbuf + coff + a * 5;
                const float o0 = s[0];
                const float o1 = s[1];
                const float o2 = s[2];
                const float o3 = s[3];
                const float obj = s[4];

                const float area_a = (ax2 - ax1) * (ay2 - ay1);
                const float acx = (ax1 + ax2) * 0.5f;
                const float acy = (ay1 + ay2) * 0.5f;

                const float bcx = o0 - 0.5f + zx;
                const float bcy = o1 - 0.5f + zy;
                const float bw  = o2 - 0.5f + (1.0f / GXN);
                const float bh  = o3 - 0.5f + (1.0f / GYN);
                const float bx1 = bcx - bw * 0.5f;
                const float bx2 = bcx + bw * 0.5f;
                const float by1 = bcy - bh * 0.5f;
                const float by2 = bcy + bh * 0.5f;

                const float iw = fminf(ax2, bx2) - fmaxf(ax1, bx1);
                const float ih = fminf(ay2, by2) - fmaxf(ay1, by1);
                const float cross = (iw > 0.0f && ih > 0.0f) ? iw * ih : 0.0f;
                const float area_b = (bx2 - bx1) * (by2 - by1);
                const float uni = area_a + area_b - cross;
                const float iou = __fdividef(cross, uni + 1e-6f);

                const float dx = bcx - acx;
                const float dy = bcy - acy;
                const float d2 = dx * dx + dy * dy;

                const float cw = fmaxf(ax2, bx2) - fminf(ax1, bx1);
                const float ch = fmaxf(ay2, by2) - fminf(ay1, by1);
                const float c2 = cw * cw + ch * ch;

                const float diou = iou - __fdividef(d2, c2);

                const float da = atana - atanf(__fdividef(bx2 - bx1, by2 - by1));
                const float v = FOUR_OVER_PI2 * da * da;
                const float alpha = __fdividef(v, 1.0f - iou + v);
                const float los = 1.0f - (diou - alpha * v);

                const float om = 1.0f - obj;
                acc_allloss += los + om;
                acc_jbb += iou;
                acc_huhuh += om;
                acc_zsd += om * om;
            }
        }

        // ---- Buffer free; refill with tile i+2 ----
        __syncthreads();
        if (i + 2 < nt && tid == 0) {
            const unsigned mb = buf ? mbar1 : mbar0;
            const unsigned db = smem_u32(bb);
            const size_t tn = (size_t)(bid + (i + 2) * GRID);
            mbar_expect_tx(mb, BUF_BYTES);
            bulk_copy(db, out + tn * OUT_FLOATS, OUT_BYTES, mb);
            bulk_copy(db + OUT_BYTES, target + tn * TGT_FLOATS, TGT_BYTES, mb);
        }
    }

    // ---- Block reduction (once per block) ----
    float vals[5];
    vals[0] = acc_allloss;
    vals[1] = acc_jbb;
    vals[2] = acc_huhuh;
    vals[3] = acc_zsd;
    vals[4] = acc_npos;

    #pragma unroll
    for (int kk = 0; kk < 5; kk++) {
        float v = vals[kk];
        v += __shfl_xor_sync(FULL, v, 16);
        v += __shfl_xor_sync(FULL, v, 8);
        v += __shfl_xor_sync(FULL, v, 4);
        v += __shfl_xor_sync(FULL, v, 2);
        v += __shfl_xor_sync(FULL, v, 1);
        vals[kk] = v;
    }
    if (lane == 0) {
        #pragma unroll
        for (int kk = 0; kk < 5; kk++) s_red[warp][kk] = vals[kk];
    }
    __syncthreads();

    if (warp == 0 && lane < 5) {
        float v = 0.0f;
        #pragma unroll
        for (int w = 0; w < NWARPS; w++) v += s_red[w][lane];
        atomicAdd(&g_acc[lane], (double)v);
    }
    __syncthreads();

    // ---- Last block finalizes and resets for next graph replay ----
    if (tid == 0) {
        __threadfence();
        const unsigned done = atomicAdd(&g_count, 1u);
        s_islast = (done == (unsigned)(gridDim.x - 1)) ? 1 : 0;
    }
    __syncthreads();

    if (s_islast && tid == 0) {
        const double a0 = atomicAdd(&g_acc[0], 0.0);
        const double a1 = atomicAdd(&g_acc[1], 0.0);
        const double a2 = atomicAdd(&g_acc[2], 0.0);
        const double a3 = atomicAdd(&g_acc[3], 0.0);
        const double npos = atomicAdd(&g_acc[4], 0.0);

        const double jsq = npos * (double)NA;
        const double qit = ((double)NCELLS - npos) * (double)NA;
        o[0] = (float)(a0 / jsq + a3 / (jsq + qit));
        o[1] = (float)(a1 / jsq);
        o[2] = (float)(a2 / jsq);

        g_acc[0] = 0.0; g_acc[1] = 0.0; g_acc[2] = 0.0;
        g_acc[3] = 0.0; g_acc[4] = 0.0;
        __threadfence();
        g_count = 0u;
    }
}

extern "C" void kernel_launch(void* const* d_in, const int* in_sizes, int n_in,
                              void* d_out, int out_size) {
    const float* out_t = (const float*)d_in[0];
    const float* target = (const float*)d_in[1];
    float* o = (float*)d_out;

    const int smem_bytes = 2 * BUF_FLOATS * (int)sizeof(float); // 64512
    static int configured = 0;
    if (!configured) {
        cudaFuncSetAttribute(loss_kernel,
                             cudaFuncAttributeMaxDynamicSharedMemorySize,
                             smem_bytes);
        configured = 1;
    }
    loss_kernel<<<GRID, TPB, smem_bytes>>>(out_t, target, o);
}